// round 4
// baseline (speedup 1.0000x reference)
#include <cuda_runtime.h>
#include <math.h>

#define TT   1460
#define GG   5000
#define CH   15              // steps per chunk (= UH length, ring period)
#define NCH  98              // 98*15 = 1470 >= 1460
#define ROWF 96              // 32 cells * 3 floats per timestep row

// ---- packed f32x2 + approx transcendental helpers -----------------------------
#define PACK2(d, lo, hi)   asm("mov.b64 %0, {%1, %2};" : "=l"(d) : "f"(lo), "f"(hi))
#define UNPACK2(lo, hi, d) asm("mov.b64 {%0, %1}, %2;" : "=f"(lo), "=f"(hi) : "l"(d))
#define FMA2(d, a, b, c)   asm("fma.rn.f32x2 %0, %1, %2, %3;" : "=l"(d) : "l"(a), "l"(b), "l"(c))

__device__ __forceinline__ float lg2a(float x) { float r; asm("lg2.approx.f32 %0, %1;" : "=f"(r) : "f"(x)); return r; }
__device__ __forceinline__ float ex2a(float x) { float r; asm("ex2.approx.f32 %0, %1;" : "=f"(r) : "f"(x)); return r; }

__device__ __forceinline__ void cp_async16(void* sm, const void* gm) {
    unsigned a = (unsigned)__cvta_generic_to_shared(sm);
    asm volatile("cp.async.cg.shared.global [%0], [%1], 16;\n" :: "r"(a), "l"(gm));
}
__device__ __forceinline__ void cp_commit() { asm volatile("cp.async.commit_group;\n" ::: "memory"); }
__device__ __forceinline__ void cp_wait1()  { asm volatile("cp.async.wait_group 1;\n" ::: "memory"); }
__device__ __forceinline__ void cp_wait0()  { asm volatile("cp.async.wait_group 0;\n" ::: "memory"); }

__global__ __launch_bounds__(96, 1)
void hmets_kernel(const float* __restrict__ x,
                  const float* __restrict__ par,
                  float* __restrict__ out)
{
    // double-buffered stage queues
    __shared__ __align__(16) float  xbuf[2][CH * ROWF];   // raw forcings
    __shared__ __align__(16) float4 pre4[2][CH * 32];     // (rain, snow, pot_fr, dT)
    __shared__            float     retb[2][CH * 32];     // RET
    __shared__ __align__(16) float4 htb [2][CH * 32];     // (ht0, ht1, ht2+ht3, 0)

    const int tid  = threadIdx.x;
    const int wid  = tid >> 5;
    const int lane = tid & 31;
    const int g0   = blockIdx.x * 32;
    const int g    = g0 + lane;
    const bool active  = (g < GG);
    const bool fullblk = (g0 + 32 <= GG);

    // -------- per-cell parameters (all warps compute; one-time cost) ----------------
    const float* pr = par + ((size_t)(TT - 1) * GG + (active ? g : (GG - 1))) * 20;
    float s[20];
#pragma unroll
    for (int i = 0; i < 20; i++) {
        float v = __ldg(pr + i);
        s[i] = 1.0f / (1.0f + expf(-v));
    }
    const float ddf_min = 20.0f * s[0];
    const float ddf_sum = ddf_min + 20.0f * s[1];
    const float Tbm     = -2.0f + 5.0f * s[2];
    const float Kcum    = 0.01f + 0.19f * s[3];
    const float fcmin   = 0.1f * s[4];
    const float fc_sum  = fcmin + 0.01f + 0.24f * s[5];
    const float Ccum    = 0.005f + 0.045f * s[6];
    const float Tbf     = -5.0f + 7.0f * s[7];
    const float Kf      = 5.0f * s[8];
    const float efe     = s[9];
    const float ETe     = 3.0f * s[10];
    const float cRun    = s[11];
    const float cV2P    = 1e-5f + (0.02f - 1e-5f) * s[12];
    const float cVad    = 0.1f * s[13];
    const float cPh     = 1e-5f + (0.01f - 1e-5f) * s[14];
    const float Vmax    = 0.001f + (500.0f - 0.001f) * s[15];
    const float invVmax = 1.0f / Vmax;

    // -------- gamma UH weights, packed (uh1[l], uh2[l]) — conv warp only uses -------
    unsigned long long uhp[CH];
    {
        float a1 = 0.3f  + (20.0f - 0.3f)  * s[16];
        float b1 = 0.01f + (5.0f  - 0.01f) * s[17];
        float a2 = 0.5f  + (13.0f - 0.5f)  * s[18];
        float b2 = 0.15f + (1.5f  - 0.15f) * s[19];
        float i1 = 1.0f / b1, i2 = 1.0f / b2;
        float w1[CH], w2[CH];
        float n1 = 0.f, n2 = 0.f;
#pragma unroll
        for (int l = 0; l < CH; l++) {
            float t  = (float)l + 0.5f;
            w1[l] = powf(t, a1 - 1.0f) * expf(-t * i1);
            w2[l] = powf(t, a2 - 1.0f) * expf(-t * i2);
            n1 += w1[l]; n2 += w2[l];
        }
        n1 = 1.0f / n1; n2 = 1.0f / n2;
#pragma unroll
        for (int l = 0; l < CH; l++) PACK2(uhp[l], w1[l] * n1, w2[l] * n2);
    }

    // -------- forcing tile prefetch (chunk granularity, cp.async, zero-padded) ------
    auto prefetch = [&](int c) {
        float* dst = xbuf[c & 1];
        int t0 = c * CH;
        if (fullblk) {
            for (int j = lane; j < CH * 24; j += 32) {     // 24 float4 per row
                int row = j / 24, q = j - row * 24;
                if (t0 + row < TT) {
                    const float* gp = x + (size_t)(t0 + row) * (GG * 3) + g0 * 3 + q * 4;
                    cp_async16(dst + row * ROWF + q * 4, gp);
                } else {
                    float4 z = {0.f, 0.f, 0.f, 0.f};
                    *(float4*)(dst + row * ROWF + q * 4) = z;
                }
            }
        } else {
            for (int j = lane; j < CH * ROWF; j += 32) {
                int row = j / ROWF, q = j - row * ROWF;
                int cell = g0 + q / 3;
                dst[row * ROWF + q] = (cell < GG && t0 + row < TT)
                    ? __ldg(x + (size_t)(t0 + row) * (GG * 3) + g0 * 3 + q) : 0.0f;
            }
        }
        cp_commit();
    };

    // -------- per-warp persistent state ---------------------------------------------
    float S = 1e-5f, W = 1e-5f, C = 1e-5f, P = 1e-5f;
    float V = 0.5f * Vmax;
    unsigned long long hpk[CH];
#pragma unroll
    for (int l = 0; l < CH; l++) hpk[l] = 0ull;

    if (wid == 0) prefetch(0);
    __syncthreads();

    // ============================ 3-stage chunk pipeline ============================
    for (int c = 0; c < NCH + 2; c++) {
        if (wid == 0 && c < NCH) {
            // ---- stage 0: prefetch next chunk, derive forcing values ----
            if (c + 1 < NCH) { prefetch(c + 1); cp_wait1(); }
            else             { cp_wait0(); }
            const float* rb = xbuf[c & 1] + lane * 3;
            float4* pb = pre4[c & 1] + lane;
            float*  eb = retb[c & 1] + lane;
#pragma unroll
            for (int u = 0; u < CH; u++) {
                float Pp = rb[u * ROWF + 0];
                float Tt = rb[u * ROWF + 1];
                float PE = rb[u * ROWF + 2];
                float rain = (Tt >= 0.0f) ? Pp : 0.0f;
                float snow = Pp - rain;
                float base = fmaxf(Tbf - Tt, 1e-5f);
                float potf = Kf * ex2a(efe * lg2a(base));
                float dT   = Tt - Tbm;
                float4 v; v.x = rain; v.y = snow; v.z = potf; v.w = dT;
                pb[u * 32] = v;
                eb[u * 32] = ETe * PE;
            }
        } else if (wid == 1 && c >= 1 && c - 1 < NCH) {
            // ---- stage 1: sequential state scan ----
            const int b = (c - 1) & 1;
            const float4* pb = pre4[b] + lane;
            const float*  eb = retb[b] + lane;
            float4* hb = htb[b] + lane;
#pragma unroll
            for (int u = 0; u < CH; u++) {
                float4 f   = pb[u * 32];          // rain, snow, potf, dT
                float  RET = eb[u * 32];

                float fr = fminf(f.z, W);
                W -= fr;
                S += fr;

                float ddf  = fminf(ddf_sum, ddf_min * fmaf(Kcum, C, 1.0f));
                float S1   = S + f.y;
                float melt = fminf(fmaxf(ddf * f.w, 0.0f), S1);
                S = S1 - melt;
                C = (S > 1e-5f) ? (C + melt) : 0.0f;

                float wrf  = fmaxf(fc_sum * fmaf(-Ccum, C, 1.0f), fcmin);
                float wr   = wrf * S;
                float wtmp = W + melt + f.x;
                float wa   = fmaxf(wtmp - wr, 0.0f);
                W = (wa > 0.0f) ? wr : wtmp;

                float ratio = V * invVmax;
                float cr    = cRun * ratio;
                float ht0   = cr * wa;
                float infil = fmaxf(wa - ht0 - RET, 0.0f);
                float ht1   = cr * ratio * infil;
                float ht2   = cVad * V;
                float v2p   = cV2P * V;
                V = V + infil - ht1 - ht2 - v2p;
                float over = fmaxf(V - Vmax, 0.0f);
                V -= over;
                ht1 += over;
                P += v2p;
                float ht3 = cPh * P;
                P -= ht3;

                float4 h; h.x = ht0; h.y = ht1; h.z = ht2 + ht3; h.w = 0.0f;
                hb[u * 32] = h;
            }
        } else if (wid == 2 && c >= 2) {
            // ---- stage 2: 15-tap dual gamma-UH conv + output store ----
            const int cc = c - 2;
            const float4* hb = htb[cc & 1] + lane;
            float* op = out + (size_t)cc * CH * GG + g;
            const int t0 = cc * CH;
#pragma unroll
            for (int u = 0; u < CH; u++) {
                float4 h = hb[u * 32];
                PACK2(hpk[u], h.x, h.y);
                unsigned long long qp = 0ull;
#pragma unroll
                for (int l = 0; l < CH; l++)
                    FMA2(qp, uhp[l], hpk[(u - l + CH) % CH], qp);
                float qlo, qhi;
                UNPACK2(qlo, qhi, qp);
                float q = h.z + qlo + qhi;
                if (active && (t0 + u) < TT) op[u * GG] = q;
            }
        }
        __syncthreads();
    }
}

extern "C" void kernel_launch(void* const* d_in, const int* in_sizes, int n_in,
                              void* d_out, int out_size)
{
    (void)in_sizes; (void)n_in; (void)out_size;
    const float* x   = (const float*)d_in[0];   // x_phy  [1460, 5000, 3]
    const float* par = (const float*)d_in[1];   // params [1460, 5000, 20]
    float* out = (float*)d_out;                 // Q      [1460, 5000]
    hmets_kernel<<<(GG + 31) / 32, 96>>>(x, par, out);
}